// round 17
// baseline (speedup 1.0000x reference)
#include <cuda_runtime.h>
#include <cuda_fp16.h>

#define B   256
#define N   8192
#define C   32768
#define NSE 524288

#define TRANS_BLOCKS ((C / 128) * (B / 32))  // 256 * 8 = 2048
#define PREP_BLOCKS  (NSE / 4 / 256)         // 512
#define MAX_E 128                            // smem-staged edges per node (mean 64, max ~95)

// Scratch (device globals — no allocation allowed). SoA edge arrays.
__device__ float4 g_pT4[(size_t)C * B / 8];           // exp(child_ll) transposed [C][B] fp16
__device__ __align__(16) unsigned g_eoff[NSE + 4];    // col*512 byte offset
__device__ __align__(16) unsigned g_ew[NSE + 4];      // exp(log_w) as dup'd half2
__device__ int g_row_start[N + 1];

// K1 (fused): transpose+exp+fp16-pack for pT (128c x 32b tiles), AND edge prep.
__global__ __launch_bounds__(256) void prep_kernel(const float* __restrict__ ll,
                                                   const float* __restrict__ logw,
                                                   const int*   __restrict__ rows,
                                                   const int*   __restrict__ cols) {
    int t = threadIdx.x;
    if (blockIdx.x < TRANS_BLOCKS) {
        __shared__ float tile[32][129];
        int c0 = (blockIdx.x & (C / 128 - 1)) * 128;
        int b0 = (blockIdx.x >> 8) * 32;
        int row = t >> 3;
        int v   = t & 7;
        const float4* src = (const float4*)(ll + (size_t)(b0 + row) * C + c0);
#pragma unroll
        for (int j = 0; j < 4; j++) {
            float4 x = __ldg(&src[v + j * 8]);
            int col = (v + j * 8) * 4;
            tile[row][col + 0] = x.x;
            tile[row][col + 1] = x.y;
            tile[row][col + 2] = x.z;
            tile[row][col + 3] = x.w;
        }
        __syncthreads();
        int c_loc = t >> 1;
        int bofs  = (t & 1) * 16;
        uint4 outv[2];
        __half* hh = (__half*)outv;
#pragma unroll
        for (int j = 0; j < 16; j++)
            hh[j] = __float2half_rn(__expf(tile[bofs + j][c_loc]));
        __half* pT = (__half*)g_pT4;
        uint4* dst = (uint4*)&pT[(size_t)(c0 + c_loc) * B + b0 + bofs];
        dst[0] = outv[0];
        dst[1] = outv[1];
    } else {
        int e4 = (blockIdx.x - TRANS_BLOCKS) * 256 + t;
        int e  = e4 * 4;
        float4 lw = __ldg(&((const float4*)logw)[e4]);
        int4   cc = __ldg(&((const int4*)cols)[e4]);
        int4   rr = __ldg(&((const int4*)rows)[e4]);
        __half2 w0 = __float2half2_rn(__expf(lw.x));
        __half2 w1 = __float2half2_rn(__expf(lw.y));
        __half2 w2 = __float2half2_rn(__expf(lw.z));
        __half2 w3 = __float2half2_rn(__expf(lw.w));
        uint4 wv = make_uint4(*(unsigned*)&w0, *(unsigned*)&w1,
                              *(unsigned*)&w2, *(unsigned*)&w3);
        uint4 ov = make_uint4((unsigned)cc.x * 512u, (unsigned)cc.y * 512u,
                              (unsigned)cc.z * 512u, (unsigned)cc.w * 512u);
        ((uint4*)g_ew)[e4]   = wv;
        ((uint4*)g_eoff)[e4] = ov;
        int rprev = (e == 0) ? -1 : __ldg(&rows[e - 1]);
        if (rr.x != rprev) g_row_start[rr.x] = e + 0;
        if (rr.y != rr.x)  g_row_start[rr.y] = e + 1;
        if (rr.z != rr.y)  g_row_start[rr.z] = e + 2;
        if (rr.w != rr.z)  g_row_start[rr.w] = e + 3;
        if (e == 0)        g_row_start[N]    = NSE;
    }
}

// fp16 accumulate one edge (4 batches): 2 HFMA2 + 1 HADD2
#define EDGEK(Wu, pv) {                                        \
    __half2 w2 = *(__half2*)&(Wu);                             \
    const __half2* ph = (const __half2*)&(pv);                 \
    hA = __hfma2(w2, ph[0], hA); hB = __hfma2(w2, ph[1], hB);  \
    hW = __hadd2(hW, w2); }

// fp32 scalar path: offset ofs (lvalue), dup'd-half2 weight wu (lvalue)
#define EDGES(ofs, wu) {                                       \
    float we = __low2float(*(__half2*)&(wu));                  \
    float2 pv = __ldg((const float2*)(pTb + (ofs)));           \
    const __half2* ph = (const __half2*)&pv;                   \
    float2 f;                                                  \
    f = __half22float2(ph[0]); a0 = fmaf(we, f.x, a0); a1 = fmaf(we, f.y, a1); \
    f = __half22float2(ph[1]); a2 = fmaf(we, f.x, a2); a3 = fmaf(we, f.y, a3); \
    wsum += we; }

// K2: 2 warps per node (128 batches each, 4/lane), SoA smem slabs staged once
// per node, chunk-8 hot loop with low register liveness -> 6 blocks/SM.
__global__ __launch_bounds__(256, 6) void sum_kernel(float* __restrict__ out) {
    __shared__ float s_res[4][B];
    __shared__ __align__(16) unsigned soff[4][MAX_E];
    __shared__ __align__(16) unsigned swt[4][MAX_E];
    int warp = threadIdx.x >> 5;
    int lane = threadIdx.x & 31;
    int nloc = warp >> 1;                 // node within block (0..3)
    int half = warp & 1;                  // 128-batch half
    int node = blockIdx.x * 4 + nloc;

    int e0 = g_row_start[node];
    int e1 = g_row_start[node + 1];
    int estart = e0 & ~3;                 // 16B-aligned start in both SoA arrays
    int off    = e0 - estart;             // 0..3
    int total  = e1 - estart;
    int cpy    = total < MAX_E ? total : MAX_E;

    // Stage SoA slabs once per node: lanes 0..nchunks-1 -> offsets,
    // lanes 32..32+nchunks-1 -> weights (each <=32 x 16B chunks).
    {
        int lane64 = half * 32 + lane;
        int nchunks16 = (cpy + 3) >> 2;   // <= 32
        if (lane64 < nchunks16) {
            unsigned sdst = (unsigned)__cvta_generic_to_shared(&soff[nloc][0]) + lane64 * 16;
            const char* gsrc = (const char*)(g_eoff + estart) + lane64 * 16;
            asm volatile("cp.async.ca.shared.global [%0], [%1], 16;"
                         :: "r"(sdst), "l"(gsrc));
        } else if (lane64 >= 32 && lane64 < 32 + nchunks16) {
            int k = lane64 - 32;
            unsigned sdst = (unsigned)__cvta_generic_to_shared(&swt[nloc][0]) + k * 16;
            const char* gsrc = (const char*)(g_ew + estart) + k * 16;
            asm volatile("cp.async.ca.shared.global [%0], [%1], 16;"
                         :: "r"(sdst), "l"(gsrc));
        }
        asm volatile("cp.async.commit_group;");
        asm volatile("cp.async.wait_group 0;" ::: "memory");
    }
    __syncthreads();

    const char* pTb = (const char*)g_pT4 + half * 256 + lane * 8;
    const __half2 hz = __float2half2_rn(0.f);
    float a0 = 0.f, a1 = 0.f, a2 = 0.f, a3 = 0.f, wsum = 0.f;

    const uint4* so4 = (const uint4*)&soff[nloc][0];   // 4 offsets per uint4
    const uint4* sw4 = (const uint4*)&swt[nloc][0];    // 4 weights per uint4
    int i = off;
    while (i < cpy && (i & 3)) { EDGES(soff[nloc][i], swt[nloc][i]); i++; }
    for (; i + 8 <= cpy; i += 8) {
        // 2 LDS.128 of offsets -> 8 independent gathers -> 2 LDS.128 of weights
        uint4 O0 = so4[(i >> 2) + 0];
        uint4 O1 = so4[(i >> 2) + 1];
        float2 p0 = __ldg((const float2*)(pTb + O0.x));
        float2 p1 = __ldg((const float2*)(pTb + O0.y));
        float2 p2 = __ldg((const float2*)(pTb + O0.z));
        float2 p3 = __ldg((const float2*)(pTb + O0.w));
        float2 p4 = __ldg((const float2*)(pTb + O1.x));
        float2 p5 = __ldg((const float2*)(pTb + O1.y));
        float2 p6 = __ldg((const float2*)(pTb + O1.z));
        float2 p7 = __ldg((const float2*)(pTb + O1.w));
        uint4 W0 = sw4[(i >> 2) + 0];
        uint4 W1 = sw4[(i >> 2) + 1];
        __half2 hA = hz, hB = hz, hW = hz;
        EDGEK(W0.x, p0) EDGEK(W0.y, p1) EDGEK(W0.z, p2) EDGEK(W0.w, p3)
        EDGEK(W1.x, p4) EDGEK(W1.y, p5) EDGEK(W1.z, p6) EDGEK(W1.w, p7)
        float2 f;
        f = __half22float2(hA); a0 += f.x; a1 += f.y;
        f = __half22float2(hB); a2 += f.x; a3 += f.y;
        wsum += __low2float(hW);
    }
    for (; i < cpy; i++) { EDGES(soff[nloc][i], swt[nloc][i]); }
    // overflow beyond MAX_E (statistically never; correctness guard)
    for (int e = estart + cpy; e < e1; e++) {
        unsigned ofs = __ldg(&g_eoff[e]);
        unsigned wu  = __ldg(&g_ew[e]);
        EDGES(ofs, wu);
    }

    float lz = __logf(wsum);
    float4 r = make_float4(__logf(a0) - lz, __logf(a1) - lz,
                           __logf(a2) - lz, __logf(a3) - lz);
    *(float4*)&s_res[nloc][half * 128 + lane * 4] = r;
    __syncthreads();

    // Transposed write-out: thread b writes 4 consecutive nodes (16B)
    int bb = threadIdx.x;   // 0..255 == B
    float4 v = make_float4(s_res[0][bb], s_res[1][bb], s_res[2][bb], s_res[3][bb]);
    *(float4*)(out + (size_t)bb * N + (size_t)blockIdx.x * 4) = v;
}

extern "C" void kernel_launch(void* const* d_in, const int* in_sizes, int n_in,
                              void* d_out, int out_size) {
    const float* child_ll = (const float*)d_in[0];  // [B, C]
    const float* log_w    = (const float*)d_in[1];  // [NSE]
    const int*   rows     = (const int*)d_in[2];    // [NSE], sorted
    const int*   cols     = (const int*)d_in[3];    // [NSE]
    float*       out      = (float*)d_out;          // [B, N]

    prep_kernel<<<TRANS_BLOCKS + PREP_BLOCKS, 256>>>(child_ll, log_w, rows, cols);
    sum_kernel<<<N / 4, 256>>>(out);
}